// round 1
// baseline (speedup 1.0000x reference)
#include <cuda_runtime.h>
#include <math.h>

#define T_FRAMES 64
#define SPIRAL_S 9

// Ping-pong scratch (static device globals; no allocation).
// A holds conv outputs / dense output: max = 64*5023*32 = 10,287,104 floats
// B holds pooled tensors:              max = 64*5023*64 = 20,574,208 floats
__device__ float g_bufA[10287104];
__device__ float g_bufB[20574208];

// -------------------------------------------------------------------------
// zero
__global__ void zero_kernel(float* __restrict__ p, int n) {
    int i = blockIdx.x * blockDim.x + threadIdx.x;
    int stride = gridDim.x * blockDim.x;
    for (; i < n; i += stride) p[i] = 0.0f;
}

// -------------------------------------------------------------------------
// dense: out[t, j] = latent[t,:] . W0[j,:] + b0[j]   (t<64, j<2560)
// warp per output element, shuffle reduce.
__global__ void dense_kernel(const float* __restrict__ latent,
                             const float* __restrict__ W0,
                             const float* __restrict__ b0,
                             float* __restrict__ out) {
    int t = blockIdx.y;
    int warp = threadIdx.x >> 5;
    int lane = threadIdx.x & 31;
    int j = blockIdx.x * 8 + warp;
    if (j >= 2560) return;
    const float* lrow = latent + t * 128;
    const float* wrow = W0 + (size_t)j * 128;
    float acc = 0.f;
#pragma unroll
    for (int k = lane; k < 128; k += 32) acc += lrow[k] * wrow[k];
#pragma unroll
    for (int o = 16; o > 0; o >>= 1) acc += __shfl_down_sync(0xffffffffu, acc, o);
    if (lane == 0) out[(size_t)t * 2560 + j] = acc + b0[j];
}

// -------------------------------------------------------------------------
// pool (sparse up-transform scatter-add):
// out[t, rows[e], c] += x[t, cols[e], c] * vals[e]
// block = one nnz entry, threads over channels, loop over t.
__global__ void pool_kernel(const float* __restrict__ x,
                            const int* __restrict__ rows,
                            const int* __restrict__ cols,
                            const float* __restrict__ vals,
                            float* __restrict__ out,
                            int n_in, int n_out, int C) {
    int e = blockIdx.x;
    int c = threadIdx.x;
    int r = rows[e];
    int cl = cols[e];
    float v = vals[e];
    const float* xp = x + (size_t)cl * C + c;
    float* op = out + (size_t)r * C + c;
    size_t sx = (size_t)n_in * C;
    size_t so = (size_t)n_out * C;
#pragma unroll 4
    for (int t = 0; t < T_FRAMES; t++)
        atomicAdd(op + t * so, xp[t * sx] * v);
}

// -------------------------------------------------------------------------
// spiral conv:
//   out[t, n, co] = act( sum_{s,ci} x[t, idx[n,s], ci] * W[co, s*CIN+ci] + b[co] )
// Block = (vertex n, t-chunk). Gathered rows staged in shared; W staged in
// shared per-KT tile transposed [kk][co] (conflict-free: threads map to co
// strided by CG). Register tile: RT t-values x RC co-values per thread.
// MODE 0 = ELU, MODE 1 = no act + actor add (final layer).
template <int CIN, int COUT, int TCH, int RT, int RC, int MODE>
__global__ void conv_kernel(const float* __restrict__ x,
                            const int* __restrict__ spiral,
                            const float* __restrict__ W,
                            const float* __restrict__ bias,
                            const float* __restrict__ actor,
                            float* __restrict__ out,
                            int nverts) {
    constexpr int K   = SPIRAL_S * CIN;
    constexpr int KP  = K + 1;          // padded xg row (kills bank conflicts for RT=1 path)
    constexpr int CG  = COUT / RC;      // co groups
    constexpr int TG  = TCH / RT;       // t groups
    constexpr int NTH = CG * TG;
    constexpr int KT  = 32;             // K tile (K is a multiple of 32 for all levels)
    constexpr int CP  = COUT + 1;       // padded Wt row

    extern __shared__ float sm[];
    float* xg = sm;                 // TCH * KP
    float* Wt = sm + TCH * KP;      // KT * CP, layout [kk][co]
    __shared__ int vidx[SPIRAL_S];

    int n  = blockIdx.x;
    int t0 = blockIdx.y * TCH;
    int tid = threadIdx.x;

    if (tid < SPIRAL_S) vidx[tid] = spiral[n * SPIRAL_S + tid];
    __syncthreads();

    // gather spiral neighborhood rows into shared (coalesced over ci)
    for (int i = tid; i < TCH * K; i += NTH) {
        int tl = i / K;
        int k  = i - tl * K;
        int s  = k / CIN;
        int ci = k - s * CIN;
        xg[tl * KP + k] = x[((size_t)(t0 + tl) * nverts + vidx[s]) * CIN + ci];
    }

    int cog = tid % CG;
    int tg  = tid / CG;

    float acc[RT][RC];
#pragma unroll
    for (int r = 0; r < RT; r++)
#pragma unroll
        for (int c = 0; c < RC; c++) acc[r][c] = 0.f;

    for (int k0 = 0; k0 < K; k0 += KT) {
        __syncthreads();
        // load W tile: global coalesced along k, shared write stride CP (conflict-free)
        for (int i = tid; i < COUT * KT; i += NTH) {
            int co = i / KT;
            int kk = i - co * KT;
            Wt[kk * CP + co] = W[(size_t)co * K + k0 + kk];
        }
        __syncthreads();
#pragma unroll
        for (int kk = 0; kk < KT; kk++) {
            float xv[RT];
#pragma unroll
            for (int r = 0; r < RT; r++)
                xv[r] = xg[(tg * RT + r) * KP + k0 + kk];
#pragma unroll
            for (int c = 0; c < RC; c++) {
                float wv = Wt[kk * CP + cog + c * CG];
#pragma unroll
                for (int r = 0; r < RT; r++)
                    acc[r][c] += xv[r] * wv;
            }
        }
    }

    // epilogue
#pragma unroll
    for (int c = 0; c < RC; c++) {
        int co = cog + c * CG;
        float bv = bias[co];
        float av = (MODE == 1) ? actor[(size_t)n * 3 + co] : 0.f;
#pragma unroll
        for (int r = 0; r < RT; r++) {
            int t = t0 + tg * RT + r;
            float v = acc[r][c] + bv;
            if (MODE == 0) v = (v > 0.f) ? v : (expf(v) - 1.f);
            else           v += av;
            out[((size_t)t * nverts + n) * COUT + co] = v;
        }
    }
}

// -------------------------------------------------------------------------
extern "C" void kernel_launch(void* const* d_in, const int* in_sizes, int n_in_cnt,
                              void* d_out, int out_size) {
    const float* latent = (const float*)d_in[0];
    const float* actor  = (const float*)d_in[1];
    const int* sp0 = (const int*)d_in[2];
    const int* sp1 = (const int*)d_in[3];
    const int* sp2 = (const int*)d_in[4];
    const int* sp3 = (const int*)d_in[5];
    const int*   up0r = (const int*)d_in[6];
    const int*   up0c = (const int*)d_in[7];
    const float* up0v = (const float*)d_in[8];
    const int*   up1r = (const int*)d_in[9];
    const int*   up1c = (const int*)d_in[10];
    const float* up1v = (const float*)d_in[11];
    const int*   up2r = (const int*)d_in[12];
    const int*   up2c = (const int*)d_in[13];
    const float* up2v = (const float*)d_in[14];
    const int*   up3r = (const int*)d_in[15];
    const int*   up3c = (const int*)d_in[16];
    const float* up3v = (const float*)d_in[17];
    const float* W0 = (const float*)d_in[18];
    const float* b0 = (const float*)d_in[19];
    const float* W1 = (const float*)d_in[20];
    const float* b1 = (const float*)d_in[21];
    const float* W2 = (const float*)d_in[22];
    const float* b2 = (const float*)d_in[23];
    const float* W3 = (const float*)d_in[24];
    const float* b3 = (const float*)d_in[25];
    const float* W4 = (const float*)d_in[26];
    const float* b4 = (const float*)d_in[27];
    const float* Wf = (const float*)d_in[28];
    const float* bf = (const float*)d_in[29];
    float* out = (float*)d_out;

    int nnz0 = in_sizes[6];
    int nnz1 = in_sizes[9];
    int nnz2 = in_sizes[12];
    int nnz3 = in_sizes[15];

    float *A, *B;
    cudaGetSymbolAddress((void**)&A, g_bufA);
    cudaGetSymbolAddress((void**)&B, g_bufB);

    // dynamic smem sizes per conv instantiation
    const int SM_C3 = (16 * (9 * 128 + 1) + 32 * (128 + 1)) * 4; // 90,304
    const int SM_C2 = (16 * (9 * 128 + 1) + 32 * (64 + 1)) * 4;  // 82,112
    const int SM_C1 = (32 * (9 * 64 + 1) + 32 * (64 + 1)) * 4;   // 82,176
    const int SM_C0 = (32 * (9 * 64 + 1) + 32 * (32 + 1)) * 4;   // 78,080
    const int SM_CF = (64 * (9 * 32 + 1) + 32 * (3 + 1)) * 4;    // 74,496

    cudaFuncSetAttribute(conv_kernel<128, 128, 16, 4, 4, 0>,
                         cudaFuncAttributeMaxDynamicSharedMemorySize, SM_C3);
    cudaFuncSetAttribute(conv_kernel<128, 64, 16, 4, 2, 0>,
                         cudaFuncAttributeMaxDynamicSharedMemorySize, SM_C2);
    cudaFuncSetAttribute(conv_kernel<64, 64, 32, 4, 4, 0>,
                         cudaFuncAttributeMaxDynamicSharedMemorySize, SM_C1);
    cudaFuncSetAttribute(conv_kernel<64, 32, 32, 4, 2, 0>,
                         cudaFuncAttributeMaxDynamicSharedMemorySize, SM_C0);
    cudaFuncSetAttribute(conv_kernel<32, 3, 64, 1, 3, 1>,
                         cudaFuncAttributeMaxDynamicSharedMemorySize, SM_CF);

    // ---- dense: latent[64,128] @ W0^T -> A as [64, 20, 128]
    {
        dim3 g(320, 64);
        dense_kernel<<<g, 256>>>(latent, W0, b0, A);
    }

    // ---- level 3: pool 20->79 (C=128), conv 128->128
    {
        int zc = 64 * 79 * 128;
        zero_kernel<<<2048, 256>>>(B, zc);
        pool_kernel<<<nnz3, 128>>>(A, up3r, up3c, up3v, B, 20, 79, 128);
        dim3 g(79, 4);
        conv_kernel<128, 128, 16, 4, 4, 0><<<g, 128, SM_C3>>>(B, sp3, W1, b1, nullptr, A, 79);
    }

    // ---- level 2: pool 79->314 (C=128), conv 128->64
    {
        int zc = 64 * 314 * 128;
        zero_kernel<<<4096, 256>>>(B, zc);
        pool_kernel<<<nnz2, 128>>>(A, up2r, up2c, up2v, B, 79, 314, 128);
        dim3 g(314, 4);
        conv_kernel<128, 64, 16, 4, 2, 0><<<g, 128, SM_C2>>>(B, sp2, W2, b2, nullptr, A, 314);
    }

    // ---- level 1: pool 314->1256 (C=64), conv 64->64
    {
        int zc = 64 * 1256 * 64;
        zero_kernel<<<4096, 256>>>(B, zc);
        pool_kernel<<<nnz1, 64>>>(A, up1r, up1c, up1v, B, 314, 1256, 64);
        dim3 g(1256, 2);
        conv_kernel<64, 64, 32, 4, 4, 0><<<g, 128, SM_C1>>>(B, sp1, W3, b3, nullptr, A, 1256);
    }

    // ---- level 0: pool 1256->5023 (C=64), conv 64->32
    {
        int zc = 64 * 5023 * 64;
        zero_kernel<<<8192, 256>>>(B, zc);
        pool_kernel<<<nnz0, 64>>>(A, up0r, up0c, up0v, B, 1256, 5023, 64);
        dim3 g(5023, 2);
        conv_kernel<64, 32, 32, 4, 2, 0><<<g, 128, SM_C0>>>(B, sp0, W4, b4, nullptr, A, 5023);
    }

    // ---- final: conv 32->3 on level 0, + actor, into d_out
    {
        dim3 g(5023, 1);
        conv_kernel<32, 3, 64, 1, 3, 1><<<g, 64, SM_CF>>>(A, sp0, Wf, bf, actor, out, 5023);
    }

    (void)in_sizes; (void)n_in_cnt; (void)out_size; (void)bf;
}

// round 2
// speedup vs baseline: 2.8713x; 2.8713x over previous
#include <cuda_runtime.h>
#include <math.h>

#define T_FRAMES 64
#define SPIRAL_S 9

// -------------------- static device scratch (no allocations) --------------------
__device__ float g_bufA[10287104];   // conv outputs / dense output
__device__ float g_bufB[20574208];   // pooled tensors
__device__ float g_WT[277344];       // transposed weights [k][co] per layer
__device__ int   g_ptr[6680];        // CSR row pointers (all 4 levels, +1 slots)
__device__ int   g_cnt[6680];        // histogram / placement counters
__device__ int   g_eid[20016];       // CSR entry ids (sorted per row -> deterministic)
__device__ int   g_ccol[20016];      // CSR cols
__device__ float g_cval[20016];      // CSR vals

struct CsrDesc {
    const int*   rows[4];
    const int*   cols[4];
    const float* vals[4];
    int nnz[4];
    int nnzOff[5];
    int nout[4];
    int ptrOff[4];
    int rowOff[5];
    int totNnz;
    int totRows;
};

struct TDesc {
    const float* W[5];
    int K[5];
    int C[5];
    int off[5];
    int tot;
};

// -------------------- weight transpose: WT[k*C+c] = W[c*K+k] --------------------
__global__ void transpose_all(TDesc td, float* __restrict__ WT) {
    int i = blockIdx.x * blockDim.x + threadIdx.x;
    int st = gridDim.x * blockDim.x;
    for (; i < td.tot; i += st) {
        int l = 0, o = i;
        while (l < 4 && o >= td.K[l] * td.C[l]) { o -= td.K[l] * td.C[l]; l++; }
        int k = o / td.C[l];
        int c = o - k * td.C[l];
        WT[td.off[l] + o] = td.W[l][(size_t)c * td.K[l] + k];
    }
}

// -------------------- CSR build (deterministic) --------------------
__global__ void zero_int(int* __restrict__ p, int n) {
    int i = blockIdx.x * blockDim.x + threadIdx.x;
    if (i < n) p[i] = 0;
}

__global__ void hist_kernel(CsrDesc cd, int* __restrict__ cnt) {
    int e = blockIdx.x * blockDim.x + threadIdx.x;
    if (e >= cd.totNnz) return;
    int l = (e < cd.nnzOff[1]) ? 0 : (e < cd.nnzOff[2]) ? 1 : (e < cd.nnzOff[3]) ? 2 : 3;
    int el = e - cd.nnzOff[l];
    int r = cd.rows[l][el];
    atomicAdd(&cnt[cd.ptrOff[l] + r], 1);
}

// one block per level; 1024 threads; n <= 5023 -> chunk of 5 per thread
__global__ void scan_kernel(const int* __restrict__ cnt, int* __restrict__ ptr, CsrDesc cd) {
    int l = blockIdx.x;
    int n = cd.nout[l];
    int pbase = cd.ptrOff[l];
    int nb = cd.nnzOff[l];
    int tid = threadIdx.x;
    int v[5], loc[5];
    int s = 0;
#pragma unroll
    for (int j = 0; j < 5; j++) {
        int idx = tid * 5 + j;
        loc[j] = s;
        v[j] = (idx < n) ? cnt[pbase + idx] : 0;
        s += v[j];
    }
    __shared__ int sm[1024];
    sm[tid] = s;
    __syncthreads();
    for (int off = 1; off < 1024; off <<= 1) {
        int t = (tid >= off) ? sm[tid - off] : 0;
        __syncthreads();
        sm[tid] += t;
        __syncthreads();
    }
    int ex = (tid > 0) ? sm[tid - 1] : 0;
#pragma unroll
    for (int j = 0; j < 5; j++) {
        int idx = tid * 5 + j;
        if (idx < n) ptr[pbase + idx] = nb + ex + loc[j];
    }
    if (tid == 0) ptr[pbase + n] = nb + cd.nnz[l];
}

__global__ void place_kernel(CsrDesc cd, const int* __restrict__ ptr,
                             int* __restrict__ cnt, int* __restrict__ eid) {
    int e = blockIdx.x * blockDim.x + threadIdx.x;
    if (e >= cd.totNnz) return;
    int l = (e < cd.nnzOff[1]) ? 0 : (e < cd.nnzOff[2]) ? 1 : (e < cd.nnzOff[3]) ? 2 : 3;
    int el = e - cd.nnzOff[l];
    int r = cd.rows[l][el];
    int pos = ptr[cd.ptrOff[l] + r] + atomicAdd(&cnt[cd.ptrOff[l] + r], 1);
    eid[pos] = el;
}

// sort each row segment by entry id (deterministic order), emit cols/vals
__global__ void segsort_kernel(CsrDesc cd, const int* __restrict__ ptr,
                               int* __restrict__ eid, int* __restrict__ ccol,
                               float* __restrict__ cval) {
    int g = blockIdx.x * blockDim.x + threadIdx.x;
    if (g >= cd.totRows) return;
    int l = (g < cd.rowOff[1]) ? 0 : (g < cd.rowOff[2]) ? 1 : (g < cd.rowOff[3]) ? 2 : 3;
    int r = g - cd.rowOff[l];
    int j0 = ptr[cd.ptrOff[l] + r];
    int j1 = ptr[cd.ptrOff[l] + r + 1];
    for (int a = j0 + 1; a < j1; a++) {
        int key = eid[a];
        int b = a - 1;
        while (b >= j0 && eid[b] > key) { eid[b + 1] = eid[b]; b--; }
        eid[b + 1] = key;
    }
    for (int j = j0; j < j1; j++) {
        int e = eid[j];
        ccol[j] = cd.cols[l][e];
        cval[j] = cd.vals[l][e];
    }
}

// -------------------- gather pool: out[t,r,c] = sum_j val*x[t,col,c] --------------------
template <int C>
__global__ void pool_gather(const float* __restrict__ x, float* __restrict__ out,
                            const int* __restrict__ ptr, const int* __restrict__ ccol,
                            const float* __restrict__ cval, int n_in, int n_out) {
    int r = blockIdx.x;
    int c = threadIdx.x;
    int j0 = ptr[r], j1 = ptr[r + 1];
    int deg = j1 - j0;
    __shared__ int scol[64];
    __shared__ float sval[64];
    int dm = deg < 64 ? deg : 64;
    if (c < dm) { scol[c] = ccol[j0 + c]; sval[c] = cval[j0 + c]; }
    __syncthreads();
    size_t sx = (size_t)n_in * C;
    size_t so = (size_t)n_out * C;
    for (int t = 0; t < T_FRAMES; t += 4) {
        float a0 = 0.f, a1 = 0.f, a2 = 0.f, a3 = 0.f;
        for (int j = 0; j < dm; j++) {
            float v = sval[j];
            size_t base = ((size_t)t * n_in + scol[j]) * C + c;
            a0 += v * x[base];
            a1 += v * x[base + sx];
            a2 += v * x[base + 2 * sx];
            a3 += v * x[base + 3 * sx];
        }
        for (int j = 64; j < deg; j++) {  // safety tail (deg>64 ~ impossible)
            int cl = ccol[j0 + j];
            float v = cval[j0 + j];
            size_t base = ((size_t)t * n_in + cl) * C + c;
            a0 += v * x[base];
            a1 += v * x[base + sx];
            a2 += v * x[base + 2 * sx];
            a3 += v * x[base + 3 * sx];
        }
        size_t ob = ((size_t)t * n_out + r) * C + c;
        out[ob] = a0;
        out[ob + so] = a1;
        out[ob + 2 * so] = a2;
        out[ob + 3 * so] = a3;
    }
}

// -------------------- dense: out[t,j] = latent[t,:].W0[j,:] + b0[j] --------------------
__global__ void dense_kernel(const float* __restrict__ latent,
                             const float* __restrict__ W0,
                             const float* __restrict__ b0,
                             float* __restrict__ out) {
    int t = blockIdx.y;
    int warp = threadIdx.x >> 5;
    int lane = threadIdx.x & 31;
    int j = blockIdx.x * 8 + warp;
    if (j >= 2560) return;
    const float* lrow = latent + t * 128;
    const float* wrow = W0 + (size_t)j * 128;
    float acc = 0.f;
#pragma unroll
    for (int k = lane; k < 128; k += 32) acc += lrow[k] * wrow[k];
#pragma unroll
    for (int o = 16; o > 0; o >>= 1) acc += __shfl_down_sync(0xffffffffu, acc, o);
    if (lane == 0) out[(size_t)t * 2560 + j] = acc + b0[j];
}

// -------------------- spiral conv v2: streamed-K GEMM tile --------------------
// out[t,n,co] = elu( sum_k xg[t,k] * WT[k,co] + b[co] ), xg gathered via spiral.
// Block: (vertex n, t-chunk TCH, co-chunk CON). Threads = (TCH/RT)*(CON/4).
template <int CIN, int COUT, int CON, int TCH, int RT>
__global__ void conv_kernel(const float* __restrict__ x, const int* __restrict__ spiral,
                            const float* __restrict__ WT, const float* __restrict__ bias,
                            float* __restrict__ out, int nverts) {
    constexpr int K = SPIRAL_S * CIN;
    constexpr int KT = 32;
    constexpr int XS = KT + 1;
    constexpr int TG = TCH / RT;
    constexpr int CG = CON / 4;
    constexpr int NTH = TG * CG;

    __shared__ float xg[TCH * XS];
    __shared__ float wt[KT * CON];
    __shared__ int vidx[SPIRAL_S];

    int n = blockIdx.x;
    int t0 = blockIdx.y * TCH;
    int co0 = blockIdx.z * CON;
    int tid = threadIdx.x;

    if (tid < SPIRAL_S) vidx[tid] = spiral[n * SPIRAL_S + tid];

    int tg = tid / CG;
    int cog = tid - tg * CG;

    float acc[RT][4];
#pragma unroll
    for (int r = 0; r < RT; r++)
#pragma unroll
        for (int c = 0; c < 4; c++) acc[r][c] = 0.f;

    for (int k0 = 0; k0 < K; k0 += KT) {
        __syncthreads();
        int s = k0 / CIN;
        int ci0 = k0 - s * CIN;
        int v = vidx[s];
#pragma unroll
        for (int i = tid; i < TCH * KT; i += NTH) {
            int tl = i >> 5;
            int lane = i & 31;
            xg[tl * XS + lane] = x[((size_t)(t0 + tl) * nverts + v) * CIN + ci0 + lane];
        }
#pragma unroll
        for (int i = tid; i < KT * CG; i += NTH) {
            int kk = i / CG;
            int cq = i - kk * CG;
            *(float4*)&wt[kk * CON + cq * 4] =
                *(const float4*)&WT[(size_t)(k0 + kk) * COUT + co0 + cq * 4];
        }
        __syncthreads();
#pragma unroll
        for (int kk = 0; kk < KT; kk++) {
            float4 wv = *(const float4*)&wt[kk * CON + cog * 4];
#pragma unroll
            for (int r = 0; r < RT; r++) {
                float xv = xg[(tg * RT + r) * XS + kk];
                acc[r][0] += xv * wv.x;
                acc[r][1] += xv * wv.y;
                acc[r][2] += xv * wv.z;
                acc[r][3] += xv * wv.w;
            }
        }
    }

    float4 bv = *(const float4*)&bias[co0 + cog * 4];
#pragma unroll
    for (int r = 0; r < RT; r++) {
        int t = t0 + tg * RT + r;
        float4 o;
        float v0 = acc[r][0] + bv.x;
        float v1 = acc[r][1] + bv.y;
        float v2 = acc[r][2] + bv.z;
        float v3 = acc[r][3] + bv.w;
        o.x = (v0 > 0.f) ? v0 : (__expf(v0) - 1.f);
        o.y = (v1 > 0.f) ? v1 : (__expf(v1) - 1.f);
        o.z = (v2 > 0.f) ? v2 : (__expf(v2) - 1.f);
        o.w = (v3 > 0.f) ? v3 : (__expf(v3) - 1.f);
        *(float4*)&out[((size_t)t * nverts + n) * COUT + co0 + cog * 4] = o;
    }
}

// -------------------- final conv 32->3 + actor --------------------
__global__ void final_kernel(const float* __restrict__ x, const int* __restrict__ spiral,
                             const float* __restrict__ WTf,  // [288][3]
                             const float* __restrict__ bf,
                             const float* __restrict__ actor,
                             float* __restrict__ out, int nverts) {
    __shared__ float wfs[864];
    __shared__ float xg[64 * 33];
    __shared__ int vidx[SPIRAL_S];
    int n = blockIdx.x;
    int tid = threadIdx.x;  // = frame t, 64 threads
    for (int i = tid; i < 864; i += 64) wfs[i] = WTf[i];
    if (tid < SPIRAL_S) vidx[tid] = spiral[n * SPIRAL_S + tid];
    float a0 = 0.f, a1 = 0.f, a2 = 0.f;
    for (int s = 0; s < SPIRAL_S; s++) {
        __syncthreads();
        int v = vidx[s];
#pragma unroll
        for (int i = tid; i < 2048; i += 64) {
            int tl = i >> 5;
            int lane = i & 31;
            xg[tl * 33 + lane] = x[((size_t)tl * nverts + v) * 32 + lane];
        }
        __syncthreads();
#pragma unroll
        for (int kk = 0; kk < 32; kk++) {
            float xv = xg[tid * 33 + kk];
            int kb = (s * 32 + kk) * 3;
            a0 += xv * wfs[kb];
            a1 += xv * wfs[kb + 1];
            a2 += xv * wfs[kb + 2];
        }
    }
    size_t ob = ((size_t)tid * nverts + n) * 3;
    out[ob + 0] = a0 + bf[0] + actor[(size_t)n * 3 + 0];
    out[ob + 1] = a1 + bf[1] + actor[(size_t)n * 3 + 1];
    out[ob + 2] = a2 + bf[2] + actor[(size_t)n * 3 + 2];
}

// -------------------- host --------------------
extern "C" void kernel_launch(void* const* d_in, const int* in_sizes, int n_in_cnt,
                              void* d_out, int out_size) {
    const float* latent = (const float*)d_in[0];
    const float* actor  = (const float*)d_in[1];
    const int* sp0 = (const int*)d_in[2];
    const int* sp1 = (const int*)d_in[3];
    const int* sp2 = (const int*)d_in[4];
    const int* sp3 = (const int*)d_in[5];
    const int*   upr[4] = {(const int*)d_in[6], (const int*)d_in[9], (const int*)d_in[12], (const int*)d_in[15]};
    const int*   upc[4] = {(const int*)d_in[7], (const int*)d_in[10], (const int*)d_in[13], (const int*)d_in[16]};
    const float* upv[4] = {(const float*)d_in[8], (const float*)d_in[11], (const float*)d_in[14], (const float*)d_in[17]};
    const float* W0 = (const float*)d_in[18];
    const float* b0 = (const float*)d_in[19];
    const float* W1 = (const float*)d_in[20];
    const float* b1 = (const float*)d_in[21];
    const float* W2 = (const float*)d_in[22];
    const float* b2 = (const float*)d_in[23];
    const float* W3 = (const float*)d_in[24];
    const float* b3 = (const float*)d_in[25];
    const float* W4 = (const float*)d_in[26];
    const float* b4 = (const float*)d_in[27];
    const float* Wf = (const float*)d_in[28];
    const float* bf = (const float*)d_in[29];
    float* out = (float*)d_out;

    float *A, *B, *WT;
    int *ptr, *cnt, *eid, *ccol;
    float *cval;
    cudaGetSymbolAddress((void**)&A, g_bufA);
    cudaGetSymbolAddress((void**)&B, g_bufB);
    cudaGetSymbolAddress((void**)&WT, g_WT);
    cudaGetSymbolAddress((void**)&ptr, g_ptr);
    cudaGetSymbolAddress((void**)&cnt, g_cnt);
    cudaGetSymbolAddress((void**)&eid, g_eid);
    cudaGetSymbolAddress((void**)&ccol, g_ccol);
    cudaGetSymbolAddress((void**)&cval, g_cval);

    const int LEV[5] = {5023, 1256, 314, 79, 20};
    int nnz[4] = {in_sizes[6], in_sizes[9], in_sizes[12], in_sizes[15]};

    // ---- weight transposes (once per launch) ----
    TDesc td;
    td.W[0] = W1; td.K[0] = 1152; td.C[0] = 128;
    td.W[1] = W2; td.K[1] = 1152; td.C[1] = 64;
    td.W[2] = W3; td.K[2] = 576;  td.C[2] = 64;
    td.W[3] = W4; td.K[3] = 576;  td.C[3] = 32;
    td.W[4] = Wf; td.K[4] = 288;  td.C[4] = 3;
    int off = 0;
    for (int l = 0; l < 5; l++) { td.off[l] = off; off += td.K[l] * td.C[l]; }
    td.tot = off;
    transpose_all<<<(td.tot + 255) / 256, 256>>>(td, WT);

    // ---- CSR build (all 4 levels) ----
    CsrDesc cd;
    int nzo = 0;
    for (int l = 0; l < 4; l++) {
        cd.rows[l] = upr[l]; cd.cols[l] = upc[l]; cd.vals[l] = upv[l];
        cd.nnz[l] = nnz[l];
        cd.nnzOff[l] = nzo; nzo += nnz[l];
        cd.nout[l] = LEV[l];
    }
    cd.nnzOff[4] = nzo;
    cd.totNnz = nzo;
    int ro = 0;
    for (int l = 0; l < 4; l++) {
        cd.rowOff[l] = ro;
        cd.ptrOff[l] = ro + l;
        ro += LEV[l];
    }
    cd.rowOff[4] = ro;
    cd.totRows = ro;
    int ptrSlots = ro + 4;

    zero_int<<<(ptrSlots + 255) / 256, 256>>>(cnt, ptrSlots);
    hist_kernel<<<(cd.totNnz + 255) / 256, 256>>>(cd, cnt);
    scan_kernel<<<4, 1024>>>(cnt, ptr, cd);
    zero_int<<<(ptrSlots + 255) / 256, 256>>>(cnt, ptrSlots);
    place_kernel<<<(cd.totNnz + 255) / 256, 256>>>(cd, ptr, cnt, eid);
    segsort_kernel<<<(cd.totRows + 255) / 256, 256>>>(cd, ptr, eid, ccol, cval);

    // ---- dense: latent -> A [64, 20, 128] ----
    {
        dim3 g(320, 64);
        dense_kernel<<<g, 256>>>(latent, W0, b0, A);
    }

    // ---- level 3: pool 20->79 (C=128), conv 128->128 ----
    pool_gather<128><<<79, 128>>>(A, B, ptr + cd.ptrOff[3], ccol, cval, 20, 79);
    conv_kernel<128, 128, 64, 16, 4><<<dim3(79, 4, 2), 64>>>(B, sp3, WT + td.off[0], b1, A, 79);

    // ---- level 2: pool 79->314 (C=128), conv 128->64 ----
    pool_gather<128><<<314, 128>>>(A, B, ptr + cd.ptrOff[2], ccol, cval, 79, 314);
    conv_kernel<128, 64, 64, 16, 4><<<dim3(314, 4, 1), 64>>>(B, sp2, WT + td.off[1], b2, A, 314);

    // ---- level 1: pool 314->1256 (C=64), conv 64->64 ----
    pool_gather<64><<<1256, 64>>>(A, B, ptr + cd.ptrOff[1], ccol, cval, 314, 1256);
    conv_kernel<64, 64, 64, 32, 4><<<dim3(1256, 2, 1), 128>>>(B, sp1, WT + td.off[2], b3, A, 1256);

    // ---- level 0: pool 1256->5023 (C=64), conv 64->32 ----
    pool_gather<64><<<5023, 64>>>(A, B, ptr + cd.ptrOff[0], ccol, cval, 1256, 5023);
    conv_kernel<64, 32, 32, 32, 4><<<dim3(5023, 2, 1), 64>>>(B, sp0, WT + td.off[3], b4, A, 5023);

    // ---- final conv 32->3 + actor -> d_out ----
    final_kernel<<<5023, 64>>>(A, sp0, WT + td.off[4], bf, actor, out, 5023);

    (void)in_sizes; (void)n_in_cnt; (void)out_size;
}

// round 3
// speedup vs baseline: 3.8409x; 1.3376x over previous
#include <cuda_runtime.h>
#include <math.h>

#define T_FRAMES 64
#define SPIRAL_S 9

// -------------------- static device scratch (no allocations) --------------------
__device__ float g_bufA[10287104];   // conv outputs / dense output
__device__ float g_bufB[20574208];   // pooled tensors
__device__ float g_WT[277344];       // packed weights (tf32 frag layout; final layer plain)
__device__ int   g_ptr[6680];        // CSR row pointers
__device__ int   g_cnt[6680];        // histogram / placement counters
__device__ int   g_eid[20016];       // CSR entry ids
__device__ int   g_ccol[20016];      // CSR cols
__device__ float g_cval[20016];      // CSR vals

struct CsrDesc {
    const int*   rows[4];
    const int*   cols[4];
    const float* vals[4];
    int nnz[4];
    int nnzOff[5];
    int nout[4];
    int ptrOff[4];
    int rowOff[5];
    int totNnz;
    int totRows;
};

struct TDesc {
    const float* W[5];
    int K[5];
    int C[5];
    int off[5];
    int tot;
};

__device__ __forceinline__ unsigned f2tf32(float f) {
    unsigned u;
    asm("cvt.rna.tf32.f32 %0, %1;" : "=r"(u) : "f"(f));
    return u;
}

// -------------------- weight pack --------------------
// Layers 0..3: tf32-converted, B-fragment order:
//   dst = ((k/8)*(C/8) + co/8)*64 + (co%8)*8 + (k%4)*2 + ((k%8)/4)
// Layer 4 (final): plain transpose [k][c], fp32.
__global__ void pack_weights(TDesc td, float* __restrict__ WT) {
    int i = blockIdx.x * blockDim.x + threadIdx.x;
    int st = gridDim.x * blockDim.x;
    for (; i < td.tot; i += st) {
        int l = 0, o = i;
        while (l < 4 && o >= td.K[l] * td.C[l]) { o -= td.K[l] * td.C[l]; l++; }
        int K = td.K[l], C = td.C[l];
        int k = o / C;
        int c = o - k * C;
        float v = td.W[l][(size_t)c * K + k];
        if (l < 4) {
            int dst = ((k >> 3) * (C >> 3) + (c >> 3)) * 64 + (c & 7) * 8 + (k & 3) * 2 + ((k & 7) >> 2);
            WT[td.off[l] + dst] = __uint_as_float(f2tf32(v));
        } else {
            WT[td.off[l] + o] = v;
        }
    }
}

// -------------------- CSR build (deterministic) --------------------
__global__ void zero_int(int* __restrict__ p, int n) {
    int i = blockIdx.x * blockDim.x + threadIdx.x;
    if (i < n) p[i] = 0;
}

__global__ void hist_kernel(CsrDesc cd, int* __restrict__ cnt) {
    int e = blockIdx.x * blockDim.x + threadIdx.x;
    if (e >= cd.totNnz) return;
    int l = (e < cd.nnzOff[1]) ? 0 : (e < cd.nnzOff[2]) ? 1 : (e < cd.nnzOff[3]) ? 2 : 3;
    int el = e - cd.nnzOff[l];
    int r = cd.rows[l][el];
    atomicAdd(&cnt[cd.ptrOff[l] + r], 1);
}

__global__ void scan_kernel(const int* __restrict__ cnt, int* __restrict__ ptr, CsrDesc cd) {
    int l = blockIdx.x;
    int n = cd.nout[l];
    int pbase = cd.ptrOff[l];
    int nb = cd.nnzOff[l];
    int tid = threadIdx.x;
    int v[5], loc[5];
    int s = 0;
#pragma unroll
    for (int j = 0; j < 5; j++) {
        int idx = tid * 5 + j;
        loc[j] = s;
        v[j] = (idx < n) ? cnt[pbase + idx] : 0;
        s += v[j];
    }
    __shared__ int sm[1024];
    sm[tid] = s;
    __syncthreads();
    for (int off = 1; off < 1024; off <<= 1) {
        int t = (tid >= off) ? sm[tid - off] : 0;
        __syncthreads();
        sm[tid] += t;
        __syncthreads();
    }
    int ex = (tid > 0) ? sm[tid - 1] : 0;
#pragma unroll
    for (int j = 0; j < 5; j++) {
        int idx = tid * 5 + j;
        if (idx < n) ptr[pbase + idx] = nb + ex + loc[j];
    }
    if (tid == 0) ptr[pbase + n] = nb + cd.nnz[l];
}

__global__ void place_kernel(CsrDesc cd, const int* __restrict__ ptr,
                             int* __restrict__ cnt, int* __restrict__ eid) {
    int e = blockIdx.x * blockDim.x + threadIdx.x;
    if (e >= cd.totNnz) return;
    int l = (e < cd.nnzOff[1]) ? 0 : (e < cd.nnzOff[2]) ? 1 : (e < cd.nnzOff[3]) ? 2 : 3;
    int el = e - cd.nnzOff[l];
    int r = cd.rows[l][el];
    int pos = ptr[cd.ptrOff[l] + r] + atomicAdd(&cnt[cd.ptrOff[l] + r], 1);
    eid[pos] = el;
}

__global__ void segsort_kernel(CsrDesc cd, const int* __restrict__ ptr,
                               int* __restrict__ eid, int* __restrict__ ccol,
                               float* __restrict__ cval) {
    int g = blockIdx.x * blockDim.x + threadIdx.x;
    if (g >= cd.totRows) return;
    int l = (g < cd.rowOff[1]) ? 0 : (g < cd.rowOff[2]) ? 1 : (g < cd.rowOff[3]) ? 2 : 3;
    int r = g - cd.rowOff[l];
    int j0 = ptr[cd.ptrOff[l] + r];
    int j1 = ptr[cd.ptrOff[l] + r + 1];
    for (int a = j0 + 1; a < j1; a++) {
        int key = eid[a];
        int b = a - 1;
        while (b >= j0 && eid[b] > key) { eid[b + 1] = eid[b]; b--; }
        eid[b + 1] = key;
    }
    for (int j = j0; j < j1; j++) {
        int e = eid[j];
        ccol[j] = cd.cols[l][e];
        cval[j] = cd.vals[l][e];
    }
}

// -------------------- gather pool --------------------
template <int C>
__global__ void pool_gather(const float* __restrict__ x, float* __restrict__ out,
                            const int* __restrict__ ptr, const int* __restrict__ ccol,
                            const float* __restrict__ cval, int n_in, int n_out) {
    int r = blockIdx.x;
    int c = threadIdx.x;
    int j0 = ptr[r], j1 = ptr[r + 1];
    int deg = j1 - j0;
    __shared__ int scol[64];
    __shared__ float sval[64];
    int dm = deg < 64 ? deg : 64;
    if (c < dm) { scol[c] = ccol[j0 + c]; sval[c] = cval[j0 + c]; }
    __syncthreads();
    size_t sx = (size_t)n_in * C;
    size_t so = (size_t)n_out * C;
    for (int t = 0; t < T_FRAMES; t += 4) {
        float a0 = 0.f, a1 = 0.f, a2 = 0.f, a3 = 0.f;
        for (int j = 0; j < dm; j++) {
            float v = sval[j];
            size_t base = ((size_t)t * n_in + scol[j]) * C + c;
            a0 += v * x[base];
            a1 += v * x[base + sx];
            a2 += v * x[base + 2 * sx];
            a3 += v * x[base + 3 * sx];
        }
        for (int j = 64; j < deg; j++) {
            int cl = ccol[j0 + j];
            float v = cval[j0 + j];
            size_t base = ((size_t)t * n_in + cl) * C + c;
            a0 += v * x[base];
            a1 += v * x[base + sx];
            a2 += v * x[base + 2 * sx];
            a3 += v * x[base + 3 * sx];
        }
        size_t ob = ((size_t)t * n_out + r) * C + c;
        out[ob] = a0;
        out[ob + so] = a1;
        out[ob + 2 * so] = a2;
        out[ob + 3 * so] = a3;
    }
}

// -------------------- dense --------------------
__global__ void dense_kernel(const float* __restrict__ latent,
                             const float* __restrict__ W0,
                             const float* __restrict__ b0,
                             float* __restrict__ out) {
    int t = blockIdx.y;
    int warp = threadIdx.x >> 5;
    int lane = threadIdx.x & 31;
    int j = blockIdx.x * 8 + warp;
    if (j >= 2560) return;
    const float* lrow = latent + t * 128;
    const float* wrow = W0 + (size_t)j * 128;
    float acc = 0.f;
#pragma unroll
    for (int k = lane; k < 128; k += 32) acc += lrow[k] * wrow[k];
#pragma unroll
    for (int o = 16; o > 0; o >>= 1) acc += __shfl_down_sync(0xffffffffu, acc, o);
    if (lane == 0) out[(size_t)t * 2560 + j] = acc + b0[j];
}

// -------------------- spiral conv v3: tf32 mma.sync --------------------
// Block = one vertex n (+ optional co-chunk). 4 warps cover T=64 (16 rows each).
// K streamed in 32-chunks. A fragments from xg (stride 36, conflict-free),
// B fragments pre-packed in global (coalesced tile copy, conflict-free LDS.64).
template <int CIN, int COUT, int CON>
__global__ void conv_tf32(const float* __restrict__ x, const int* __restrict__ spiral,
                          const float* __restrict__ WTf, const float* __restrict__ bias,
                          float* __restrict__ out, int nverts) {
    constexpr int K  = SPIRAL_S * CIN;
    constexpr int NT = CON / 8;                 // n-tiles per block
    constexpr int BROW = (COUT / 8) * 64;       // frag floats per k8-row (full layer)

    __shared__ float xg[64 * 36];
    __shared__ float bt[4 * NT * 64];
    __shared__ int vidx[SPIRAL_S];

    int tid = threadIdx.x;
    int warp = tid >> 5;
    int lane = tid & 31;
    int n = blockIdx.x;
    int co0 = blockIdx.z * CON;

    if (tid < SPIRAL_S) vidx[tid] = spiral[n * SPIRAL_S + tid];

    float acc[NT][4];
#pragma unroll
    for (int nt = 0; nt < NT; nt++)
#pragma unroll
        for (int c = 0; c < 4; c++) acc[nt][c] = 0.f;

    unsigned* xgu = (unsigned*)xg;
    int rr = lane >> 2;
    int cc = lane & 3;
    int t0w = warp * 16;

    for (int k0 = 0; k0 < K; k0 += 32) {
        __syncthreads();
        int s = k0 / CIN;
        int ci0 = k0 - s * CIN;
        int v = vidx[s];
        // gather + tf32 convert (coalesced 128B per warp-row)
#pragma unroll
        for (int i = tid; i < 64 * 32; i += 128) {
            int t = i >> 5;
            int ln = i & 31;
            float f = x[((size_t)t * nverts + v) * CIN + ci0 + ln];
            xgu[t * 36 + ln] = f2tf32(f);
        }
        // B tile copy (frag order, contiguous per k8-row)
        {
            const float* src = WTf + (size_t)(k0 >> 3) * BROW + (co0 >> 3) * 64;
#pragma unroll
            for (int i = tid; i < NT * 64; i += 128) {   // NT*64 float4s
                int r = i / (NT * 16);
                int c = i - r * (NT * 16);
                ((float4*)bt)[i] = ((const float4*)(src + (size_t)r * BROW))[c];
            }
        }
        __syncthreads();
#pragma unroll
        for (int ks = 0; ks < 4; ks++) {
            int kb = ks * 8;
            unsigned a0 = xgu[(t0w + rr) * 36 + kb + cc];
            unsigned a1 = xgu[(t0w + rr + 8) * 36 + kb + cc];
            unsigned a2 = xgu[(t0w + rr) * 36 + kb + cc + 4];
            unsigned a3 = xgu[(t0w + rr + 8) * 36 + kb + cc + 4];
#pragma unroll
            for (int nt = 0; nt < NT; nt++) {
                float2 bb = *(float2*)&bt[(ks * NT + nt) * 64 + lane * 2];
                unsigned b0 = __float_as_uint(bb.x);
                unsigned b1 = __float_as_uint(bb.y);
                asm volatile(
                    "mma.sync.aligned.m16n8k8.row.col.f32.tf32.tf32.f32 "
                    "{%0,%1,%2,%3}, {%4,%5,%6,%7}, {%8,%9}, {%0,%1,%2,%3};"
                    : "+f"(acc[nt][0]), "+f"(acc[nt][1]), "+f"(acc[nt][2]), "+f"(acc[nt][3])
                    : "r"(a0), "r"(a1), "r"(a2), "r"(a3), "r"(b0), "r"(b1));
            }
        }
    }

    // epilogue: bias + ELU, float2 stores
    int c2 = cc * 2;
#pragma unroll
    for (int nt = 0; nt < NT; nt++) {
        int co = co0 + nt * 8 + c2;
        float2 bv = *(const float2*)&bias[co];
        float v0 = acc[nt][0] + bv.x;
        float v1 = acc[nt][1] + bv.y;
        float v2 = acc[nt][2] + bv.x;
        float v3 = acc[nt][3] + bv.y;
        v0 = (v0 > 0.f) ? v0 : (__expf(v0) - 1.f);
        v1 = (v1 > 0.f) ? v1 : (__expf(v1) - 1.f);
        v2 = (v2 > 0.f) ? v2 : (__expf(v2) - 1.f);
        v3 = (v3 > 0.f) ? v3 : (__expf(v3) - 1.f);
        int t0 = t0w + rr;
        *(float2*)&out[((size_t)t0 * nverts + n) * COUT + co] = make_float2(v0, v1);
        *(float2*)&out[((size_t)(t0 + 8) * nverts + n) * COUT + co] = make_float2(v2, v3);
    }
}

// -------------------- final conv 32->3 + actor (fp32) --------------------
__global__ void final_kernel(const float* __restrict__ x, const int* __restrict__ spiral,
                             const float* __restrict__ WTf,  // [288][3]
                             const float* __restrict__ bf,
                             const float* __restrict__ actor,
                             float* __restrict__ out, int nverts) {
    __shared__ float wfs[864];
    __shared__ float xg[64 * 33];
    __shared__ int vidx[SPIRAL_S];
    int n = blockIdx.x;
    int tid = threadIdx.x;  // frame t, 64 threads
    for (int i = tid; i < 864; i += 64) wfs[i] = WTf[i];
    if (tid < SPIRAL_S) vidx[tid] = spiral[n * SPIRAL_S + tid];
    float a0 = 0.f, a1 = 0.f, a2 = 0.f;
    for (int s = 0; s < SPIRAL_S; s++) {
        __syncthreads();
        int v = vidx[s];
#pragma unroll
        for (int i = tid; i < 2048; i += 64) {
            int tl = i >> 5;
            int lane = i & 31;
            xg[tl * 33 + lane] = x[((size_t)tl * nverts + v) * 32 + lane];
        }
        __syncthreads();
#pragma unroll
        for (int kk = 0; kk < 32; kk++) {
            float xv = xg[tid * 33 + kk];
            int kb = (s * 32 + kk) * 3;
            a0 += xv * wfs[kb];
            a1 += xv * wfs[kb + 1];
            a2 += xv * wfs[kb + 2];
        }
    }
    size_t ob = ((size_t)tid * nverts + n) * 3;
    out[ob + 0] = a0 + bf[0] + actor[(size_t)n * 3 + 0];
    out[ob + 1] = a1 + bf[1] + actor[(size_t)n * 3 + 1];
    out[ob + 2] = a2 + bf[2] + actor[(size_t)n * 3 + 2];
}

// -------------------- host --------------------
extern "C" void kernel_launch(void* const* d_in, const int* in_sizes, int n_in_cnt,
                              void* d_out, int out_size) {
    const float* latent = (const float*)d_in[0];
    const float* actor  = (const float*)d_in[1];
    const int* sp0 = (const int*)d_in[2];
    const int* sp1 = (const int*)d_in[3];
    const int* sp2 = (const int*)d_in[4];
    const int* sp3 = (const int*)d_in[5];
    const int*   upr[4] = {(const int*)d_in[6], (const int*)d_in[9], (const int*)d_in[12], (const int*)d_in[15]};
    const int*   upc[4] = {(const int*)d_in[7], (const int*)d_in[10], (const int*)d_in[13], (const int*)d_in[16]};
    const float* upv[4] = {(const float*)d_in[8], (const float*)d_in[11], (const float*)d_in[14], (const float*)d_in[17]};
    const float* W0 = (const float*)d_in[18];
    const float* b0 = (const float*)d_in[19];
    const float* W1 = (const float*)d_in[20];
    const float* b1 = (const float*)d_in[21];
    const float* W2 = (const float*)d_in[22];
    const float* b2 = (const float*)d_in[23];
    const float* W3 = (const float*)d_in[24];
    const float* b3 = (const float*)d_in[25];
    const float* W4 = (const float*)d_in[26];
    const float* b4 = (const float*)d_in[27];
    const float* Wf = (const float*)d_in[28];
    const float* bf = (const float*)d_in[29];
    float* out = (float*)d_out;

    float *A, *B, *WT;
    int *ptr, *cnt, *eid, *ccol;
    float *cval;
    cudaGetSymbolAddress((void**)&A, g_bufA);
    cudaGetSymbolAddress((void**)&B, g_bufB);
    cudaGetSymbolAddress((void**)&WT, g_WT);
    cudaGetSymbolAddress((void**)&ptr, g_ptr);
    cudaGetSymbolAddress((void**)&cnt, g_cnt);
    cudaGetSymbolAddress((void**)&eid, g_eid);
    cudaGetSymbolAddress((void**)&ccol, g_ccol);
    cudaGetSymbolAddress((void**)&cval, g_cval);

    const int LEV[5] = {5023, 1256, 314, 79, 20};
    int nnz[4] = {in_sizes[6], in_sizes[9], in_sizes[12], in_sizes[15]};

    // ---- weight pack (tf32 frag layout for conv layers, plain for final) ----
    TDesc td;
    td.W[0] = W1; td.K[0] = 1152; td.C[0] = 128;
    td.W[1] = W2; td.K[1] = 1152; td.C[1] = 64;
    td.W[2] = W3; td.K[2] = 576;  td.C[2] = 64;
    td.W[3] = W4; td.K[3] = 576;  td.C[3] = 32;
    td.W[4] = Wf; td.K[4] = 288;  td.C[4] = 3;
    int off = 0;
    for (int l = 0; l < 5; l++) { td.off[l] = off; off += td.K[l] * td.C[l]; }
    td.tot = off;
    pack_weights<<<(td.tot + 255) / 256, 256>>>(td, WT);

    // ---- CSR build ----
    CsrDesc cd;
    int nzo = 0;
    for (int l = 0; l < 4; l++) {
        cd.rows[l] = upr[l]; cd.cols[l] = upc[l]; cd.vals[l] = upv[l];
        cd.nnz[l] = nnz[l];
        cd.nnzOff[l] = nzo; nzo += nnz[l];
        cd.nout[l] = LEV[l];
    }
    cd.nnzOff[4] = nzo;
    cd.totNnz = nzo;
    int ro = 0;
    for (int l = 0; l < 4; l++) {
        cd.rowOff[l] = ro;
        cd.ptrOff[l] = ro + l;
        ro += LEV[l];
    }
    cd.rowOff[4] = ro;
    cd.totRows = ro;
    int ptrSlots = ro + 4;

    zero_int<<<(ptrSlots + 255) / 256, 256>>>(cnt, ptrSlots);
    hist_kernel<<<(cd.totNnz + 255) / 256, 256>>>(cd, cnt);
    scan_kernel<<<4, 1024>>>(cnt, ptr, cd);
    zero_int<<<(ptrSlots + 255) / 256, 256>>>(cnt, ptrSlots);
    place_kernel<<<(cd.totNnz + 255) / 256, 256>>>(cd, ptr, cnt, eid);
    segsort_kernel<<<(cd.totRows + 255) / 256, 256>>>(cd, ptr, eid, ccol, cval);

    // ---- dense: latent -> A [64, 20, 128] ----
    {
        dim3 g(320, 64);
        dense_kernel<<<g, 256>>>(latent, W0, b0, A);
    }

    // ---- level 3: pool 20->79 (C=128), conv 128->128 (tf32) ----
    pool_gather<128><<<79, 128>>>(A, B, ptr + cd.ptrOff[3], ccol, cval, 20, 79);
    conv_tf32<128, 128, 64><<<dim3(79, 1, 2), 128>>>(B, sp3, WT + td.off[0], b1, A, 79);

    // ---- level 2: pool 79->314 (C=128), conv 128->64 (tf32) ----
    pool_gather<128><<<314, 128>>>(A, B, ptr + cd.ptrOff[2], ccol, cval, 79, 314);
    conv_tf32<128, 64, 64><<<dim3(314, 1, 1), 128>>>(B, sp2, WT + td.off[1], b2, A, 314);

    // ---- level 1: pool 314->1256 (C=64), conv 64->64 (tf32) ----
    pool_gather<64><<<1256, 64>>>(A, B, ptr + cd.ptrOff[1], ccol, cval, 314, 1256);
    conv_tf32<64, 64, 64><<<dim3(1256, 1, 1), 128>>>(B, sp1, WT + td.off[2], b3, A, 1256);

    // ---- level 0: pool 1256->5023 (C=64), conv 64->32 (tf32) ----
    pool_gather<64><<<5023, 64>>>(A, B, ptr + cd.ptrOff[0], ccol, cval, 1256, 5023);
    conv_tf32<64, 32, 32><<<dim3(5023, 1, 1), 128>>>(B, sp0, WT + td.off[3], b4, A, 5023);

    // ---- final conv 32->3 + actor -> d_out ----
    final_kernel<<<5023, 64>>>(A, sp0, WT + td.off[4], bf, actor, out, 5023);

    (void)in_sizes; (void)n_in_cnt; (void)out_size;
}

// round 5
// speedup vs baseline: 7.7371x; 2.0144x over previous
#include <cuda_runtime.h>
#include <cuda_fp16.h>
#include <math.h>
#include <stdint.h>

#define T_FRAMES 64
#define SPIRAL_S 9

// -------------------- static device scratch (no allocations) --------------------
__device__ float g_bufA[10287104];   // conv outputs / dense output (fp32)
__device__ float g_bufB[10287104];   // pooled tensors (fp16, cast)
__device__ float g_WT[277344];       // packed weights: fp16 frag images (l<4), final fp32
__device__ int   g_ptr[6680];        // CSR row pointers
__device__ int   g_cnt[6680];        // histogram counters
__device__ int   g_cnt2[6680];       // placement counters
__device__ int   g_eid[20016];       // CSR entry ids
__device__ int   g_ccol[20016];      // CSR cols
__device__ float g_cval[20016];      // CSR vals

// final-layer float weights live at this float offset inside g_WT
// (total conv halves = 1152*128+1152*64+576*64+576*32 = 276480 -> 138240 floats)
#define WT_FINAL_F32_OFF 138240

struct CsrDesc {
    const int*   rows[4];
    const int*   cols[4];
    const float* vals[4];
    int nnz[4];
    int nnzOff[5];
    int nout[4];
    int ptrOff[4];
    int rowOff[5];
    int totNnz;
    int totRows;
};

struct TDesc {
    const float* W[5];
    int K[5];
    int C[5];
    int offH[5];   // half offsets for l<4; unused for l=4
    int tot;
};

// -------------------- weight pack --------------------
// l<4: fp16 B-fragment image for mma.m16n8k16.row.col:
//   kc = k/16, kk = k%16, nt = c/8
//   lane = (c%8)*4 + ((kk>>1)&3), reg = kk>>3, h = kk&1
//   idx32 = (kc*(C/8)+nt)*64 + lane*2 + reg ; half index = idx32*2 + h
// l=4: plain transpose [k][c] fp32 at WT_FINAL_F32_OFF.
__global__ void pack_weights(TDesc td, float* __restrict__ WT) {
    __half* WH = (__half*)WT;
    int i = blockIdx.x * blockDim.x + threadIdx.x;
    int st = gridDim.x * blockDim.x;
    for (; i < td.tot; i += st) {
        int l = 0, o = i;
        while (l < 4 && o >= td.K[l] * td.C[l]) { o -= td.K[l] * td.C[l]; l++; }
        int K = td.K[l], C = td.C[l];
        int k = o / C;
        int c = o - k * C;
        float v = td.W[l][(size_t)c * K + k];
        if (l < 4) {
            int kc = k >> 4;
            int kk = k & 15;
            int nt = c >> 3;
            int lane = (c & 7) * 4 + ((kk >> 1) & 3);
            int reg = kk >> 3;
            int h = kk & 1;
            int idx32 = (kc * (C >> 3) + nt) * 64 + lane * 2 + reg;
            WH[td.offH[l] + idx32 * 2 + h] = __float2half(v);
        } else {
            WT[WT_FINAL_F32_OFF + o] = v;
        }
    }
}

// -------------------- CSR build (deterministic) --------------------
__global__ void zero2_int(int* __restrict__ p, int* __restrict__ q, int n) {
    int i = blockIdx.x * blockDim.x + threadIdx.x;
    if (i < n) { p[i] = 0; q[i] = 0; }
}

__global__ void hist_kernel(CsrDesc cd, int* __restrict__ cnt) {
    int e = blockIdx.x * blockDim.x + threadIdx.x;
    if (e >= cd.totNnz) return;
    int l = (e < cd.nnzOff[1]) ? 0 : (e < cd.nnzOff[2]) ? 1 : (e < cd.nnzOff[3]) ? 2 : 3;
    int el = e - cd.nnzOff[l];
    int r = cd.rows[l][el];
    atomicAdd(&cnt[cd.ptrOff[l] + r], 1);
}

__global__ void scan_kernel(const int* __restrict__ cnt, int* __restrict__ ptr, CsrDesc cd) {
    int l = blockIdx.x;
    int n = cd.nout[l];
    int pbase = cd.ptrOff[l];
    int nb = cd.nnzOff[l];
    int tid = threadIdx.x;
    int v[5], loc[5];
    int s = 0;
#pragma unroll
    for (int j = 0; j < 5; j++) {
        int idx = tid * 5 + j;
        loc[j] = s;
        v[j] = (idx < n) ? cnt[pbase + idx] : 0;
        s += v[j];
    }
    __shared__ int sm[1024];
    sm[tid] = s;
    __syncthreads();
    for (int off = 1; off < 1024; off <<= 1) {
        int t = (tid >= off) ? sm[tid - off] : 0;
        __syncthreads();
        sm[tid] += t;
        __syncthreads();
    }
    int ex = (tid > 0) ? sm[tid - 1] : 0;
#pragma unroll
    for (int j = 0; j < 5; j++) {
        int idx = tid * 5 + j;
        if (idx < n) ptr[pbase + idx] = nb + ex + loc[j];
    }
    if (tid == 0) ptr[pbase + n] = nb + cd.nnz[l];
}

__global__ void place_kernel(CsrDesc cd, const int* __restrict__ ptr,
                             int* __restrict__ cnt, int* __restrict__ eid) {
    int e = blockIdx.x * blockDim.x + threadIdx.x;
    if (e >= cd.totNnz) return;
    int l = (e < cd.nnzOff[1]) ? 0 : (e < cd.nnzOff[2]) ? 1 : (e < cd.nnzOff[3]) ? 2 : 3;
    int el = e - cd.nnzOff[l];
    int r = cd.rows[l][el];
    int pos = ptr[cd.ptrOff[l] + r] + atomicAdd(&cnt[cd.ptrOff[l] + r], 1);
    eid[pos] = el;
}

__global__ void segsort_kernel(CsrDesc cd, const int* __restrict__ ptr,
                               int* __restrict__ eid, int* __restrict__ ccol,
                               float* __restrict__ cval) {
    int g = blockIdx.x * blockDim.x + threadIdx.x;
    if (g >= cd.totRows) return;
    int l = (g < cd.rowOff[1]) ? 0 : (g < cd.rowOff[2]) ? 1 : (g < cd.rowOff[3]) ? 2 : 3;
    int r = g - cd.rowOff[l];
    int j0 = ptr[cd.ptrOff[l] + r];
    int j1 = ptr[cd.ptrOff[l] + r + 1];
    for (int a = j0 + 1; a < j1; a++) {
        int key = eid[a];
        int b = a - 1;
        while (b >= j0 && eid[b] > key) { eid[b + 1] = eid[b]; b--; }
        eid[b + 1] = key;
    }
    for (int j = j0; j < j1; j++) {
        int e = eid[j];
        ccol[j] = cd.cols[l][e];
        cval[j] = cd.vals[l][e];
    }
}

// -------------------- gather pool: fp32 in, fp16 out --------------------
template <int C, int TG>
__global__ void pool_gather(const float* __restrict__ x, __half* __restrict__ out,
                            const int* __restrict__ ptr, const int* __restrict__ ccol,
                            const float* __restrict__ cval, int n_in, int n_out) {
    int r = blockIdx.x;
    int tid = threadIdx.x;
    int c = tid % C;
    int tg = tid / C;
    int j0 = ptr[r], j1 = ptr[r + 1];
    int deg = j1 - j0;
    __shared__ int scol[32];
    __shared__ float sval[32];
    int dm = deg < 32 ? deg : 32;
    if (tid < dm) { scol[tid] = ccol[j0 + tid]; sval[tid] = cval[j0 + tid]; }
    __syncthreads();
    size_t sx = (size_t)n_in * C;
    size_t so = (size_t)n_out * C;
    constexpr int TL = T_FRAMES / TG;
    int t0 = tg * TL;
    for (int t = t0; t < t0 + TL; t += 4) {
        float a0 = 0.f, a1 = 0.f, a2 = 0.f, a3 = 0.f;
        for (int j = 0; j < dm; j++) {
            float v = sval[j];
            size_t base = ((size_t)t * n_in + scol[j]) * C + c;
            a0 += v * x[base];
            a1 += v * x[base + sx];
            a2 += v * x[base + 2 * sx];
            a3 += v * x[base + 3 * sx];
        }
        for (int j = 32; j < deg; j++) {
            int cl = ccol[j0 + j];
            float v = cval[j0 + j];
            size_t base = ((size_t)t * n_in + cl) * C + c;
            a0 += v * x[base];
            a1 += v * x[base + sx];
            a2 += v * x[base + 2 * sx];
            a3 += v * x[base + 3 * sx];
        }
        size_t ob = ((size_t)t * n_out + r) * C + c;
        out[ob] = __float2half(a0);
        out[ob + so] = __float2half(a1);
        out[ob + 2 * so] = __float2half(a2);
        out[ob + 3 * so] = __float2half(a3);
    }
}

// -------------------- dense --------------------
__global__ void dense_kernel(const float* __restrict__ latent,
                             const float* __restrict__ W0,
                             const float* __restrict__ b0,
                             float* __restrict__ out) {
    int t = blockIdx.y;
    int warp = threadIdx.x >> 5;
    int lane = threadIdx.x & 31;
    int j = blockIdx.x * 8 + warp;
    if (j >= 2560) return;
    const float* lrow = latent + t * 128;
    const float* wrow = W0 + (size_t)j * 128;
    float acc = 0.f;
#pragma unroll
    for (int k = lane; k < 128; k += 32) acc += lrow[k] * wrow[k];
#pragma unroll
    for (int o = 16; o > 0; o >>= 1) acc += __shfl_down_sync(0xffffffffu, acc, o);
    if (lane == 0) out[(size_t)t * 2560 + j] = acc + b0[j];
}

// -------------------- spiral conv v5: fp16 mma.m16n8k16, 2 vertices/block --------------------
// Block: 2 vertices (M=128 rows = v*64+t), co-chunk CON. 4 warps, warp w owns rows
// [32w,32w+32) = 2 m16 tiles. A tile (128 rows x 32 halves) double-buffered in smem,
// one barrier per 32-K chunk. B fragments fetched by direct LDG (L1-resident).
template <int CIN, int COUT, int CON>
__global__ void __launch_bounds__(128)
conv_fp16(const __half* __restrict__ x, const int* __restrict__ spiral,
          const uint2* __restrict__ Bpk, const float* __restrict__ bias,
          float* __restrict__ out, int nverts) {
    constexpr int K   = SPIRAL_S * CIN;
    constexpr int NCH = K / 32;
    constexpr int NT  = CON / 8;
    constexpr int NTILES = COUT / 8;   // n-tiles per k16 row in the packed image

    __shared__ __half xg[2][128 * 40];
    __shared__ int vidx[2 * SPIRAL_S];

    int tid = threadIdx.x;
    int warp = tid >> 5;
    int lane = tid & 31;
    int n0 = blockIdx.x * 2;
    int co0 = blockIdx.z * CON;
    int nt0 = co0 >> 3;

    if (tid < 2 * SPIRAL_S) {
        int v = n0 + tid / SPIRAL_S;
        if (v >= nverts) v = nverts - 1;
        vidx[tid] = spiral[v * SPIRAL_S + tid % SPIRAL_S];
    }
    __syncthreads();

    float acc[2][NT][4];
#pragma unroll
    for (int mt = 0; mt < 2; mt++)
#pragma unroll
        for (int nt = 0; nt < NT; nt++)
#pragma unroll
            for (int j = 0; j < 4; j++) acc[mt][nt][j] = 0.f;

    auto fill = [&](int c, int b) {
        int s = (c * 32) / CIN;
        int ci0 = (c * 32) % CIN;
#pragma unroll
        for (int i = tid; i < 1024; i += 128) {
            int row = i >> 3;
            int c8 = i & 7;
            int v = row >> 6;
            int t = row & 63;
            uint2 val = *(const uint2*)&x[((size_t)t * nverts + vidx[v * SPIRAL_S + s]) * CIN + ci0 + c8 * 4];
            *(uint2*)&xg[b][row * 40 + c8 * 4] = val;
        }
    };

    fill(0, 0);
    int rbase = warp * 32;
    for (int c = 0; c < NCH; c++) {
        __syncthreads();
        if (c + 1 < NCH) fill(c + 1, (c + 1) & 1);
        const __half* xb = xg[c & 1];
#pragma unroll
        for (int j = 0; j < 2; j++) {
            uint32_t a[2][4];
#pragma unroll
            for (int mt = 0; mt < 2; mt++) {
                int r = rbase + mt * 16 + (lane >> 2);
                const uint32_t* p0 = (const uint32_t*)&xb[r * 40 + j * 16 + (lane & 3) * 2];
                const uint32_t* p1 = (const uint32_t*)&xb[(r + 8) * 40 + j * 16 + (lane & 3) * 2];
                a[mt][0] = p0[0];
                a[mt][1] = p1[0];
                a[mt][2] = p0[4];
                a[mt][3] = p1[4];
            }
            int kc = c * 2 + j;
            const uint2* bp = Bpk + (size_t)(kc * NTILES + nt0) * 32 + lane;
#pragma unroll
            for (int nt = 0; nt < NT; nt++) {
                uint2 bb = bp[nt * 32];
#pragma unroll
                for (int mt = 0; mt < 2; mt++) {
                    asm volatile(
                        "mma.sync.aligned.m16n8k16.row.col.f32.f16.f16.f32 "
                        "{%0,%1,%2,%3}, {%4,%5,%6,%7}, {%8,%9}, {%0,%1,%2,%3};"
                        : "+f"(acc[mt][nt][0]), "+f"(acc[mt][nt][1]),
                          "+f"(acc[mt][nt][2]), "+f"(acc[mt][nt][3])
                        : "r"(a[mt][0]), "r"(a[mt][1]), "r"(a[mt][2]), "r"(a[mt][3]),
                          "r"(bb.x), "r"(bb.y));
                }
            }
        }
    }

    // epilogue: bias + ELU, float2 stores
#pragma unroll
    for (int mt = 0; mt < 2; mt++) {
        int row0 = rbase + mt * 16 + (lane >> 2);
#pragma unroll
        for (int half_ = 0; half_ < 2; half_++) {
            int row = row0 + half_ * 8;
            int v = row >> 6;
            int t = row & 63;
            int n = n0 + v;
            if (n >= nverts) continue;
#pragma unroll
            for (int nt = 0; nt < NT; nt++) {
                int co = co0 + nt * 8 + (lane & 3) * 2;
                float2 bv = *(const float2*)&bias[co];
                float v0 = acc[mt][nt][half_ * 2 + 0] + bv.x;
                float v1 = acc[mt][nt][half_ * 2 + 1] + bv.y;
                v0 = (v0 > 0.f) ? v0 : (__expf(v0) - 1.f);
                v1 = (v1 > 0.f) ? v1 : (__expf(v1) - 1.f);
                *(float2*)&out[((size_t)t * nverts + n) * COUT + co] = make_float2(v0, v1);
            }
        }
    }
}

// -------------------- final conv 32->3 + actor (fp32) --------------------
__global__ void final_kernel(const float* __restrict__ x, const int* __restrict__ spiral,
                             const float* __restrict__ WTf,  // [288][3]
                             const float* __restrict__ bf,
                             const float* __restrict__ actor,
                             float* __restrict__ out, int nverts) {
    __shared__ float wfs[864];
    __shared__ float xg[64 * 33];
    __shared__ int vidx[SPIRAL_S];
    int n = blockIdx.x;
    int tid = threadIdx.x;  // frame t, 64 threads
    for (int i = tid; i < 864; i += 64) wfs[i] = WTf[i];
    if (tid < SPIRAL_S) vidx[tid] = spiral[n * SPIRAL_S + tid];
    float a0 = 0.f, a1 = 0.f, a2 = 0.f;
    for (int s = 0; s < SPIRAL_S; s++) {
        __syncthreads();
        int v = vidx[s];
#pragma unroll
        for (int i = tid; i < 2048; i += 64) {
            int tl = i >> 5;
            int lane = i & 31;
            xg[tl * 33 + lane] = x[((size_t)tl * nverts + v) * 32 + lane];
        }
        __syncthreads();
#pragma unroll
        for (int kk = 0; kk < 32; kk++) {
            float xv = xg[tid * 33 + kk];
            int kb = (s * 32 + kk) * 3;
            a0 += xv * wfs[kb];
            a1 += xv * wfs[kb + 1];
            a2 += xv * wfs[kb + 2];
        }
    }
    size_t ob = ((size_t)tid * nverts + n) * 3;
    out[ob + 0] = a0 + bf[0] + actor[(size_t)n * 3 + 0];
    out[ob + 1] = a1 + bf[1] + actor[(size_t)n * 3 + 1];
    out[ob + 2] = a2 + bf[2] + actor[(size_t)n * 3 + 2];
}

// -------------------- host --------------------
extern "C" void kernel_launch(void* const* d_in, const int* in_sizes, int n_in_cnt,
                              void* d_out, int out_size) {
    const float* latent = (const float*)d_in[0];
    const float* actor  = (const float*)d_in[1];
    const int* sp0 = (const int*)d_in[2];
    const int* sp1 = (const int*)d_in[3];
    const int* sp2 = (const int*)d_in[4];
    const int* sp3 = (const int*)d_in[5];
    const int*   upr[4] = {(const int*)d_in[6], (const int*)d_in[9], (const int*)d_in[12], (const int*)d_in[15]};
    const int*   upc[4] = {(const int*)d_in[7], (const int*)d_in[10], (const int*)d_in[13], (const int*)d_in[16]};
    const float* upv[4] = {(const float*)d_in[8], (const float*)d_in[11], (const float*)d_in[14], (const float*)d_in[17]};
    const float* W0 = (const float*)d_in[18];
    const float* b0 = (const float*)d_in[19];
    const float* W1 = (const float*)d_in[20];
    const float* b1 = (const float*)d_in[21];
    const float* W2 = (const float*)d_in[22];
    const float* b2 = (const float*)d_in[23];
    const float* W3 = (const float*)d_in[24];
    const float* b3 = (const float*)d_in[25];
    const float* W4 = (const float*)d_in[26];
    const float* b4 = (const float*)d_in[27];
    const float* Wf = (const float*)d_in[28];
    const float* bf = (const float*)d_in[29];
    float* out = (float*)d_out;

    float *A, *WT;
    __half *B;
    int *ptr, *cnt, *cnt2, *eid, *ccol;
    float *cval;
    {
        float* Bf;
        cudaGetSymbolAddress((void**)&A, g_bufA);
        cudaGetSymbolAddress((void**)&Bf, g_bufB);
        B = (__half*)Bf;
    }
    cudaGetSymbolAddress((void**)&WT, g_WT);
    cudaGetSymbolAddress((void**)&ptr, g_ptr);
    cudaGetSymbolAddress((void**)&cnt, g_cnt);
    cudaGetSymbolAddress((void**)&cnt2, g_cnt2);
    cudaGetSymbolAddress((void**)&eid, g_eid);
    cudaGetSymbolAddress((void**)&ccol, g_ccol);
    cudaGetSymbolAddress((void**)&cval, g_cval);

    const int LEV[5] = {5023, 1256, 314, 79, 20};
    int nnz[4] = {in_sizes[6], in_sizes[9], in_sizes[12], in_sizes[15]};

    // ---- weight pack ----
    TDesc td;
    td.W[0] = W1; td.K[0] = 1152; td.C[0] = 128;
    td.W[1] = W2; td.K[1] = 1152; td.C[1] = 64;
    td.W[2] = W3; td.K[2] = 576;  td.C[2] = 64;
    td.W[3] = W4; td.K[3] = 576;  td.C[3] = 32;
    td.W[4] = Wf; td.K[4] = 288;  td.C[4] = 3;
    int offH = 0;
    int tot = 0;
    for (int l = 0; l < 5; l++) {
        td.offH[l] = offH;
        if (l < 4) offH += td.K[l] * td.C[l];
        tot += td.K[l] * td.C[l];
    }
    td.tot = tot;
    pack_weights<<<(td.tot + 255) / 256, 256>>>(td, WT);

    // ---- CSR build ----
    CsrDesc cd;
    int nzo = 0;
    for (int l = 0; l < 4; l++) {
        cd.rows[l] = upr[l]; cd.cols[l] = upc[l]; cd.vals[l] = upv[l];
        cd.nnz[l] = nnz[l];
        cd.nnzOff[l] = nzo; nzo += nnz[l];
        cd.nout[l] = LEV[l];
    }
    cd.nnzOff[4] = nzo;
    cd.totNnz = nzo;
    int ro = 0;
    for (int l = 0; l < 4; l++) {
        cd.rowOff[l] = ro;
        cd.ptrOff[l] = ro + l;
        ro += LEV[l];
    }
    cd.rowOff[4] = ro;
    cd.totRows = ro;
    int ptrSlots = ro + 4;

    zero2_int<<<(ptrSlots + 255) / 256, 256>>>(cnt, cnt2, ptrSlots);
    hist_kernel<<<(cd.totNnz + 255) / 256, 256>>>(cd, cnt);
    scan_kernel<<<4, 1024>>>(cnt, ptr, cd);
    place_kernel<<<(cd.totNnz + 255) / 256, 256>>>(cd, ptr, cnt2, eid);
    segsort_kernel<<<(cd.totRows + 255) / 256, 256>>>(cd, ptr, eid, ccol, cval);

    // ---- dense: latent -> A [64, 20, 128] ----
    {
        dim3 g(320, 64);
        dense_kernel<<<g, 256>>>(latent, W0, b0, A);
    }

    const uint2* BW0 = (const uint2*)((const __half*)WT + td.offH[0]);
    const uint2* BW1 = (const uint2*)((const __half*)WT + td.offH[1]);
    const uint2* BW2 = (const uint2*)((const __half*)WT + td.offH[2]);
    const uint2* BW3 = (const uint2*)((const __half*)WT + td.offH[3]);
    const float* WFf = WT + WT_FINAL_F32_OFF;

    // ---- level 3: pool 20->79 (C=128), conv 128->128 ----
    pool_gather<128, 2><<<79, 256>>>(A, B, ptr + cd.ptrOff[3], ccol, cval, 20, 79);
    conv_fp16<128, 128, 64><<<dim3(40, 1, 2), 128>>>(B, sp3, BW0, b1, A, 79);

    // ---- level 2: pool 79->314 (C=128), conv 128->64 ----
    pool_gather<128, 2><<<314, 256>>>(A, B, ptr + cd.ptrOff[2], ccol, cval, 79, 314);
    conv_fp16<128, 64, 64><<<dim3(157, 1, 1), 128>>>(B, sp2, BW1, b2, A, 314);

    // ---- level 1: pool 314->1256 (C=64), conv 64->64 ----
    pool_gather<64, 4><<<1256, 256>>>(A, B, ptr + cd.ptrOff[1], ccol, cval, 314, 1256);
    conv_fp16<64, 64, 64><<<dim3(628, 1, 1), 128>>>(B, sp1, BW2, b3, A, 1256);

    // ---- level 0: pool 1256->5023 (C=64), conv 64->32 ----
    pool_gather<64, 4><<<5023, 256>>>(A, B, ptr + cd.ptrOff[0], ccol, cval, 1256, 5023);
    conv_fp16<64, 32, 32><<<dim3(2512, 1, 1), 128>>>(B, sp0, BW3, b4, A, 5023);

    // ---- final conv 32->3 + actor -> d_out ----
    final_kernel<<<5023, 64>>>(A, sp0, WFf, bf, actor, out, 5023);

    (void)in_sizes; (void)n_in_cnt; (void)out_size;
}

// round 6
// speedup vs baseline: 9.8614x; 1.2746x over previous
#include <cuda_runtime.h>
#include <cuda_fp16.h>
#include <math.h>
#include <stdint.h>

#define T_FRAMES 64
#define SPIRAL_S 9

// -------------------- static device scratch (no allocations) --------------------
__device__ __half g_bufA[10287104];  // conv/dense outputs (fp16)
__device__ __half g_bufB[20574208];  // pooled tensors (fp16)
__device__ float  g_WT[277344];      // packed weights: fp16 frag images (l<4), final fp32
__device__ int    g_ptr[6680];       // CSR row pointers
__device__ int    g_eid[20016];      // CSR entry ids
__device__ int    g_ccol[20016];     // CSR cols
__device__ float  g_cval[20016];     // CSR vals

// final-layer float weights at this float offset inside g_WT
#define WT_FINAL_F32_OFF 138240

struct CsrDesc {
    const int*   rows[4];
    const int*   cols[4];
    const float* vals[4];
    int nnz[4];
    int nnzOff[5];
    int nout[4];
    int ptrOff[4];
};

struct TDesc {
    const float* W[5];
    int K[5];
    int C[5];
    int offH[5];
    int tot;
};

// -------------------- weight pack --------------------
__global__ void pack_weights(TDesc td, float* __restrict__ WT) {
    __half* WH = (__half*)WT;
    int i = blockIdx.x * blockDim.x + threadIdx.x;
    int st = gridDim.x * blockDim.x;
    for (; i < td.tot; i += st) {
        int l = 0, o = i;
        while (l < 4 && o >= td.K[l] * td.C[l]) { o -= td.K[l] * td.C[l]; l++; }
        int K = td.K[l], C = td.C[l];
        int k = o / C;
        int c = o - k * C;
        float v = td.W[l][(size_t)c * K + k];
        if (l < 4) {
            int kc = k >> 4;
            int kk = k & 15;
            int nt = c >> 3;
            int lane = (c & 7) * 4 + ((kk >> 1) & 3);
            int reg = kk >> 3;
            int h = kk & 1;
            int idx32 = (kc * (C >> 3) + nt) * 64 + lane * 2 + reg;
            WH[td.offH[l] + idx32 * 2 + h] = __float2half(v);
        } else {
            WT[WT_FINAL_F32_OFF + o] = v;
        }
    }
}

// -------------------- fused CSR build (one kernel, 4 blocks) --------------------
__global__ void __launch_bounds__(1024)
csr_build(CsrDesc cd, int* __restrict__ ptr, int* __restrict__ eid,
          int* __restrict__ ccol, float* __restrict__ cval) {
    __shared__ int cnt[5024];
    __shared__ int sptr[5024];
    __shared__ int ssum[1024];

    int l = blockIdx.x;
    int n = cd.nout[l];
    int nnz = cd.nnz[l];
    int nb = cd.nnzOff[l];
    int pbase = cd.ptrOff[l];
    int tid = threadIdx.x;
    const int* rows = cd.rows[l];

    for (int i = tid; i <= n; i += 1024) cnt[i] = 0;
    __syncthreads();
    for (int e = tid; e < nnz; e += 1024) atomicAdd(&cnt[rows[e]], 1);
    __syncthreads();

    // exclusive scan (5 elems/thread)
    int v[5], loc[5];
    int s = 0;
#pragma unroll
    for (int j = 0; j < 5; j++) {
        int idx = tid * 5 + j;
        loc[j] = s;
        v[j] = (idx < n) ? cnt[idx] : 0;
        s += v[j];
    }
    ssum[tid] = s;
    __syncthreads();
    for (int off = 1; off < 1024; off <<= 1) {
        int t = (tid >= off) ? ssum[tid - off] : 0;
        __syncthreads();
        ssum[tid] += t;
        __syncthreads();
    }
    int ex = (tid > 0) ? ssum[tid - 1] : 0;
#pragma unroll
    for (int j = 0; j < 5; j++) {
        int idx = tid * 5 + j;
        if (idx < n) sptr[idx] = nb + ex + loc[j];
    }
    if (tid == 0) sptr[n] = nb + nnz;
    __syncthreads();

    // re-zero counters, place entries (deterministic after per-row sort)
    for (int i = tid; i <= n; i += 1024) cnt[i] = 0;
    __syncthreads();
    for (int e = tid; e < nnz; e += 1024) {
        int r = rows[e];
        int pos = sptr[r] + atomicAdd(&cnt[r], 1);
        eid[pos] = e;
    }
    __syncthreads();

    const int* cols = cd.cols[l];
    const float* vals = cd.vals[l];
    for (int r = tid; r < n; r += 1024) {
        int j0 = sptr[r], j1 = sptr[r + 1];
        for (int a = j0 + 1; a < j1; a++) {
            int key = eid[a];
            int b = a - 1;
            while (b >= j0 && eid[b] > key) { eid[b + 1] = eid[b]; b--; }
            eid[b + 1] = key;
        }
        for (int j = j0; j < j1; j++) {
            int e = eid[j];
            ccol[j] = cols[e];
            cval[j] = vals[e];
        }
    }
    for (int i = tid; i <= n; i += 1024) ptr[pbase + i] = sptr[i];
}

// -------------------- gather pool: fp16 in, fp16 out (half2 lanes) --------------------
template <int C>
__global__ void pool_gather(const __half* __restrict__ x, __half* __restrict__ out,
                            const int* __restrict__ ptr, const int* __restrict__ ccol,
                            const float* __restrict__ cval, int n_in, int n_out) {
    constexpr int CH = C / 2;
    constexpr int TG = 256 / CH;
    constexpr int TL = T_FRAMES / TG;
    int r = blockIdx.x;
    int tid = threadIdx.x;
    int c2 = tid % CH;
    int tg = tid / CH;
    int j0 = ptr[r], j1 = ptr[r + 1];
    int deg = j1 - j0;
    __shared__ int scol[32];
    __shared__ float sval[32];
    int dm = deg < 32 ? deg : 32;
    if (tid < dm) { scol[tid] = ccol[j0 + tid]; sval[tid] = cval[j0 + tid]; }
    __syncthreads();
    size_t sx = (size_t)n_in * CH;   // row stride in half2 units
    size_t so = (size_t)n_out * CH;
    const __half2* x2 = (const __half2*)x;
    __half2* o2 = (__half2*)out;
    int t0 = tg * TL;
    for (int t = t0; t < t0 + TL; t += 4) {
        float2 a0 = make_float2(0.f, 0.f), a1 = a0, a2 = a0, a3 = a0;
        for (int j = 0; j < dm; j++) {
            float v = sval[j];
            size_t base = ((size_t)t * n_in + scol[j]) * CH + c2;
            float2 f0 = __half22float2(x2[base]);
            float2 f1 = __half22float2(x2[base + sx]);
            float2 f2 = __half22float2(x2[base + 2 * sx]);
            float2 f3 = __half22float2(x2[base + 3 * sx]);
            a0.x += v * f0.x; a0.y += v * f0.y;
            a1.x += v * f1.x; a1.y += v * f1.y;
            a2.x += v * f2.x; a2.y += v * f2.y;
            a3.x += v * f3.x; a3.y += v * f3.y;
        }
        for (int j = 32; j < deg; j++) {
            float v = cval[j0 + j];
            size_t base = ((size_t)t * n_in + ccol[j0 + j]) * CH + c2;
            float2 f0 = __half22float2(x2[base]);
            float2 f1 = __half22float2(x2[base + sx]);
            float2 f2 = __half22float2(x2[base + 2 * sx]);
            float2 f3 = __half22float2(x2[base + 3 * sx]);
            a0.x += v * f0.x; a0.y += v * f0.y;
            a1.x += v * f1.x; a1.y += v * f1.y;
            a2.x += v * f2.x; a2.y += v * f2.y;
            a3.x += v * f3.x; a3.y += v * f3.y;
        }
        size_t ob = ((size_t)t * n_out + r) * CH + c2;
        o2[ob] = __floats2half2_rn(a0.x, a0.y);
        o2[ob + so] = __floats2half2_rn(a1.x, a1.y);
        o2[ob + 2 * so] = __floats2half2_rn(a2.x, a2.y);
        o2[ob + 3 * so] = __floats2half2_rn(a3.x, a3.y);
    }
}

// -------------------- dense: fp16 out --------------------
__global__ void dense_kernel(const float* __restrict__ latent,
                             const float* __restrict__ W0,
                             const float* __restrict__ b0,
                             __half* __restrict__ out) {
    int t = blockIdx.y;
    int warp = threadIdx.x >> 5;
    int lane = threadIdx.x & 31;
    int j = blockIdx.x * 8 + warp;
    if (j >= 2560) return;
    const float* lrow = latent + t * 128;
    const float* wrow = W0 + (size_t)j * 128;
    float acc = 0.f;
#pragma unroll
    for (int k = lane; k < 128; k += 32) acc += lrow[k] * wrow[k];
#pragma unroll
    for (int o = 16; o > 0; o >>= 1) acc += __shfl_down_sync(0xffffffffu, acc, o);
    if (lane == 0) out[(size_t)t * 2560 + j] = __float2half(acc + b0[j]);
}

// -------------------- spiral conv: fp16 mma.m16n8k16, fp16 out --------------------
template <int CIN, int COUT, int CON>
__global__ void __launch_bounds__(128)
conv_fp16(const __half* __restrict__ x, const int* __restrict__ spiral,
          const uint2* __restrict__ Bpk, const float* __restrict__ bias,
          __half* __restrict__ out, int nverts) {
    constexpr int K   = SPIRAL_S * CIN;
    constexpr int NCH = K / 32;
    constexpr int NT  = CON / 8;
    constexpr int NTILES = COUT / 8;

    __shared__ __half xg[2][128 * 40];
    __shared__ int vidx[2 * SPIRAL_S];

    int tid = threadIdx.x;
    int warp = tid >> 5;
    int lane = tid & 31;
    int n0 = blockIdx.x * 2;
    int co0 = blockIdx.z * CON;
    int nt0 = co0 >> 3;

    if (tid < 2 * SPIRAL_S) {
        int v = n0 + tid / SPIRAL_S;
        if (v >= nverts) v = nverts - 1;
        vidx[tid] = spiral[v * SPIRAL_S + tid % SPIRAL_S];
    }
    __syncthreads();

    float acc[2][NT][4];
#pragma unroll
    for (int mt = 0; mt < 2; mt++)
#pragma unroll
        for (int nt = 0; nt < NT; nt++)
#pragma unroll
            for (int j = 0; j < 4; j++) acc[mt][nt][j] = 0.f;

    auto fill = [&](int c, int b) {
        int s = (c * 32) / CIN;
        int ci0 = (c * 32) % CIN;
#pragma unroll
        for (int i = tid; i < 1024; i += 128) {
            int row = i >> 3;
            int c8 = i & 7;
            int v = row >> 6;
            int t = row & 63;
            uint2 val = *(const uint2*)&x[((size_t)t * nverts + vidx[v * SPIRAL_S + s]) * CIN + ci0 + c8 * 4];
            *(uint2*)&xg[b][row * 40 + c8 * 4] = val;
        }
    };

    fill(0, 0);
    int rbase = warp * 32;
    for (int c = 0; c < NCH; c++) {
        __syncthreads();
        if (c + 1 < NCH) fill(c + 1, (c + 1) & 1);
        const __half* xb = xg[c & 1];
#pragma unroll
        for (int j = 0; j < 2; j++) {
            uint32_t a[2][4];
#pragma unroll
            for (int mt = 0; mt < 2; mt++) {
                int r = rbase + mt * 16 + (lane >> 2);
                const uint32_t* p0 = (const uint32_t*)&xb[r * 40 + j * 16 + (lane & 3) * 2];
                const uint32_t* p1 = (const uint32_t*)&xb[(r + 8) * 40 + j * 16 + (lane & 3) * 2];
                a[mt][0] = p0[0];
                a[mt][1] = p1[0];
                a[mt][2] = p0[4];
                a[mt][3] = p1[4];
            }
            int kc = c * 2 + j;
            const uint2* bp = Bpk + (size_t)(kc * NTILES + nt0) * 32 + lane;
#pragma unroll
            for (int nt = 0; nt < NT; nt++) {
                uint2 bb = bp[nt * 32];
#pragma unroll
                for (int mt = 0; mt < 2; mt++) {
                    asm volatile(
                        "mma.sync.aligned.m16n8k16.row.col.f32.f16.f16.f32 "
                        "{%0,%1,%2,%3}, {%4,%5,%6,%7}, {%8,%9}, {%0,%1,%2,%3};"
                        : "+f"(acc[mt][nt][0]), "+f"(acc[mt][nt][1]),
                          "+f"(acc[mt][nt][2]), "+f"(acc[mt][nt][3])
                        : "r"(a[mt][0]), "r"(a[mt][1]), "r"(a[mt][2]), "r"(a[mt][3]),
                          "r"(bb.x), "r"(bb.y));
                }
            }
        }
    }

    // epilogue: bias + ELU, half2 stores
#pragma unroll
    for (int mt = 0; mt < 2; mt++) {
        int row0 = rbase + mt * 16 + (lane >> 2);
#pragma unroll
        for (int hf = 0; hf < 2; hf++) {
            int row = row0 + hf * 8;
            int v = row >> 6;
            int t = row & 63;
            int n = n0 + v;
            if (n >= nverts) continue;
#pragma unroll
            for (int nt = 0; nt < NT; nt++) {
                int co = co0 + nt * 8 + (lane & 3) * 2;
                float2 bv = *(const float2*)&bias[co];
                float v0 = acc[mt][nt][hf * 2 + 0] + bv.x;
                float v1 = acc[mt][nt][hf * 2 + 1] + bv.y;
                v0 = (v0 > 0.f) ? v0 : (__expf(v0) - 1.f);
                v1 = (v1 > 0.f) ? v1 : (__expf(v1) - 1.f);
                *(__half2*)&out[((size_t)t * nverts + n) * COUT + co] = __floats2half2_rn(v0, v1);
            }
        }
    }
}

// -------------------- final conv 32->3 + actor (fp16 in, fp32 out) --------------------
__global__ void __launch_bounds__(64)
final_kernel(const __half* __restrict__ x, const int* __restrict__ spiral,
             const float* __restrict__ WTf,  // [288][3]
             const float* __restrict__ bf,
             const float* __restrict__ actor,
             float* __restrict__ out, int nverts) {
    __shared__ float wfs[864];
    __shared__ __half xg[64 * 34];   // stride 34 halves = 17 words -> conflict-free
    __shared__ int vidx[SPIRAL_S];
    int n = blockIdx.x;
    int tid = threadIdx.x;  // frame t, 64 threads
    for (int i = tid; i < 864; i += 64) wfs[i] = WTf[i];
    if (tid < SPIRAL_S) vidx[tid] = spiral[n * SPIRAL_S + tid];
    float a0 = 0.f, a1 = 0.f, a2 = 0.f;
    uint32_t* xgu = (uint32_t*)xg;
    for (int s = 0; s < SPIRAL_S; s++) {
        __syncthreads();
        int v = vidx[s];
#pragma unroll
        for (int i = tid; i < 1024; i += 64) {
            int tl = i >> 4;
            int u = i & 15;
            xgu[tl * 17 + u] = *(const uint32_t*)&x[((size_t)tl * nverts + v) * 32 + u * 2];
        }
        __syncthreads();
        int rb = tid * 17;
#pragma unroll
        for (int u = 0; u < 16; u++) {
            float2 f = __half22float2(*(const __half2*)&xgu[rb + u]);
            int kb = (s * 32 + u * 2) * 3;
            a0 += f.x * wfs[kb + 0] + f.y * wfs[kb + 3];
            a1 += f.x * wfs[kb + 1] + f.y * wfs[kb + 4];
            a2 += f.x * wfs[kb + 2] + f.y * wfs[kb + 5];
        }
    }
    size_t ob = ((size_t)tid * nverts + n) * 3;
    out[ob + 0] = a0 + bf[0] + actor[(size_t)n * 3 + 0];
    out[ob + 1] = a1 + bf[1] + actor[(size_t)n * 3 + 1];
    out[ob + 2] = a2 + bf[2] + actor[(size_t)n * 3 + 2];
}

// -------------------- host --------------------
extern "C" void kernel_launch(void* const* d_in, const int* in_sizes, int n_in_cnt,
                              void* d_out, int out_size) {
    const float* latent = (const float*)d_in[0];
    const float* actor  = (const float*)d_in[1];
    const int* sp0 = (const int*)d_in[2];
    const int* sp1 = (const int*)d_in[3];
    const int* sp2 = (const int*)d_in[4];
    const int* sp3 = (const int*)d_in[5];
    const int*   upr[4] = {(const int*)d_in[6], (const int*)d_in[9], (const int*)d_in[12], (const int*)d_in[15]};
    const int*   upc[4] = {(const int*)d_in[7], (const int*)d_in[10], (const int*)d_in[13], (const int*)d_in[16]};
    const float* upv[4] = {(const float*)d_in[8], (const float*)d_in[11], (const float*)d_in[14], (const float*)d_in[17]};
    const float* W0 = (const float*)d_in[18];
    const float* b0 = (const float*)d_in[19];
    const float* W1 = (const float*)d_in[20];
    const float* b1 = (const float*)d_in[21];
    const float* W2 = (const float*)d_in[22];
    const float* b2 = (const float*)d_in[23];
    const float* W3 = (const float*)d_in[24];
    const float* b3 = (const float*)d_in[25];
    const float* W4 = (const float*)d_in[26];
    const float* b4 = (const float*)d_in[27];
    const float* Wf = (const float*)d_in[28];
    const float* bf = (const float*)d_in[29];
    float* out = (float*)d_out;

    __half *A, *B;
    float *WT, *cval;
    int *ptr, *eid, *ccol;
    cudaGetSymbolAddress((void**)&A, g_bufA);
    cudaGetSymbolAddress((void**)&B, g_bufB);
    cudaGetSymbolAddress((void**)&WT, g_WT);
    cudaGetSymbolAddress((void**)&ptr, g_ptr);
    cudaGetSymbolAddress((void**)&eid, g_eid);
    cudaGetSymbolAddress((void**)&ccol, g_ccol);
    cudaGetSymbolAddress((void**)&cval, g_cval);

    const int LEV[5] = {5023, 1256, 314, 79, 20};
    int nnz[4] = {in_sizes[6], in_sizes[9], in_sizes[12], in_sizes[15]};

    // ---- weight pack ----
    TDesc td;
    td.W[0] = W1; td.K[0] = 1152; td.C[0] = 128;
    td.W[1] = W2; td.K[1] = 1152; td.C[1] = 64;
    td.W[2] = W3; td.K[2] = 576;  td.C[2] = 64;
    td.W[3] = W4; td.K[3] = 576;  td.C[3] = 32;
    td.W[4] = Wf; td.K[4] = 288;  td.C[4] = 3;
    int offH = 0, tot = 0;
    for (int l = 0; l < 5; l++) {
        td.offH[l] = offH;
        if (l < 4) offH += td.K[l] * td.C[l];
        tot += td.K[l] * td.C[l];
    }
    td.tot = tot;
    pack_weights<<<(td.tot + 255) / 256, 256>>>(td, WT);

    // ---- fused CSR build ----
    CsrDesc cd;
    int nzo = 0, ro = 0;
    for (int l = 0; l < 4; l++) {
        cd.rows[l] = upr[l]; cd.cols[l] = upc[l]; cd.vals[l] = upv[l];
        cd.nnz[l] = nnz[l];
        cd.nnzOff[l] = nzo; nzo += nnz[l];
        cd.nout[l] = LEV[l];
        cd.ptrOff[l] = ro + l;
        ro += LEV[l];
    }
    cd.nnzOff[4] = nzo;
    csr_build<<<4, 1024>>>(cd, ptr, eid, ccol, cval);

    // ---- dense: latent -> A [64, 20, 128] fp16 ----
    {
        dim3 g(320, 64);
        dense_kernel<<<g, 256>>>(latent, W0, b0, A);
    }

    const uint2* BW0 = (const uint2*)((const __half*)WT + td.offH[0]);
    const uint2* BW1 = (const uint2*)((const __half*)WT + td.offH[1]);
    const uint2* BW2 = (const uint2*)((const __half*)WT + td.offH[2]);
    const uint2* BW3 = (const uint2*)((const __half*)WT + td.offH[3]);
    const float* WFf = WT + WT_FINAL_F32_OFF;

    // ---- level 3: pool 20->79 (C=128), conv 128->128 ----
    pool_gather<128><<<79, 256>>>(A, B, ptr + cd.ptrOff[3], ccol, cval, 20, 79);
    conv_fp16<128, 128, 64><<<dim3(40, 1, 2), 128>>>(B, sp3, BW0, b1, A, 79);

    // ---- level 2: pool 79->314 (C=128), conv 128->64 ----
    pool_gather<128><<<314, 256>>>(A, B, ptr + cd.ptrOff[2], ccol, cval, 79, 314);
    conv_fp16<128, 64, 64><<<dim3(157, 1, 1), 128>>>(B, sp2, BW1, b2, A, 314);

    // ---- level 1: pool 314->1256 (C=64), conv 64->64 ----
    pool_gather<64><<<1256, 256>>>(A, B, ptr + cd.ptrOff[1], ccol, cval, 314, 1256);
    conv_fp16<64, 64, 64><<<dim3(628, 1, 1), 128>>>(B, sp1, BW2, b3, A, 1256);

    // ---- level 0: pool 1256->5023 (C=64), conv 64->32 ----
    pool_gather<64><<<5023, 256>>>(A, B, ptr + cd.ptrOff[0], ccol, cval, 1256, 5023);
    conv_fp16<64, 32, 32><<<dim3(2512, 1, 1), 128>>>(B, sp0, BW3, b4, A, 5023);

    // ---- final conv 32->3 + actor -> d_out ----
    final_kernel<<<5023, 64>>>(A, sp0, WFf, bf, actor, out, 5023);

    (void)in_sizes; (void)n_in_cnt; (void)out_size;
}